// round 3
// baseline (speedup 1.0000x reference)
#include <cuda_runtime.h>
#include <cuda_fp16.h>
#include <math.h>

#define BATCH 128
#define NCAP  4608
#define JDIM  8
#define CDIM  10
#define LDIM  16
#define CL    160            // CDIM*LDIM
#define NPB   64             // n's per block in pass0
#define NCHUNKS (NCAP/NPB)   // 72

typedef unsigned long long ull;

// Scratch (static device globals; no dynamic allocation allowed)
__device__ __align__(16) float g_Wt[NCAP * CL * JDIM];          // [n][c][j][l]  ~23.6 MB
__device__ __align__(16) __half g_u[(size_t)BATCH * CDIM * NCAP * LDIM]; // 188.7 MB
__device__ __align__(16) float g_s[BATCH * CDIM * LDIM];        // s0 accumulator
__device__ __align__(16) float g_v[BATCH * CDIM * LDIM];        // v0+v1 for pass2

// ---- f32x2 packed-math helpers ---------------------------------------------
__device__ __forceinline__ ull pk2(float a, float b) {
    ull r; asm("mov.b64 %0,{%1,%2};" : "=l"(r) : "f"(a), "f"(b)); return r;
}
__device__ __forceinline__ ull fma2(ull a, ull b, ull c) {
    ull d; asm("fma.rn.f32x2 %0,%1,%2,%3;" : "=l"(d) : "l"(a), "l"(b), "l"(c)); return d;
}
__device__ __forceinline__ ull add2(ull a, ull b) {
    ull d; asm("add.rn.f32x2 %0,%1,%2;" : "=l"(d) : "l"(a), "l"(b)); return d;
}
__device__ __forceinline__ float lo2(ull a) {
    float f; asm("{ .reg .b32 h; mov.b64 {%0,h}, %1; }" : "=f"(f) : "l"(a)); return f;
}
__device__ __forceinline__ float hi2(ull a) {
    float f; asm("{ .reg .b32 l; mov.b64 {l,%0}, %1; }" : "=f"(f) : "l"(a)); return f;
}
// half2 word -> packed f32x2
__device__ __forceinline__ ull h2f2(unsigned int h) {
    __half2 hh = *reinterpret_cast<__half2*>(&h);
    float2 f = __half22float2(hh);
    return pk2(f.x, f.y);
}
// packed f32x2 -> half2 word
__device__ __forceinline__ unsigned int f22h2(ull a) {
    unsigned int h;
    float lo = lo2(a), hi = hi2(a);
    asm("cvt.rn.f16x2.f32 %0, %1, %2;" : "=r"(h) : "f"(hi), "f"(lo));
    return h;
}

// ---------------------------------------------------------------------------
// Transpose W[n][j][c*16+l] -> Wt[n][c][j][l]
// ---------------------------------------------------------------------------
__global__ void transpose_W_kernel(const float* __restrict__ W) {
    int n  = blockIdx.x;
    int t  = threadIdx.x;         // c*16+l
    int c  = t >> 4, l = t & 15;
    const float* Wn = W + (size_t)n * JDIM * CL;
    float* dst = g_Wt + (size_t)n * CL * JDIM;
#pragma unroll
    for (int j = 0; j < JDIM; ++j)
        dst[(c * JDIM + j) * LDIM + l] = Wn[j * CL + t];
}

__global__ void zero_s_kernel() {
    int i = blockIdx.x * blockDim.x + threadIdx.x;
    if (i < BATCH * CDIM * LDIM) g_s[i] = 0.0f;
}

// ---------------------------------------------------------------------------
// Pass 0: u = x.W, store fp16 u in [b][c][n][l]; accumulate raw sum_n u
// (uniform softmax(0) handled by 1/C scale later).
// 640 threads: warp w -> c = w%10, b-group = w/10. Thread owns (b,c).
// ---------------------------------------------------------------------------
__global__ __launch_bounds__(640, 1) void pass0_kernel(const float* __restrict__ x) {
    __shared__ float sW[2 * CL * JDIM];     // 2 n-tiles
    __shared__ float sx[2][64 * 9];

    const int tid  = threadIdx.x;
    const int lane = tid & 31;
    const int wid  = tid >> 5;
    const int c    = wid % CDIM;
    const int bl   = (wid / CDIM) * 32 + lane;
    const int b    = blockIdx.x * 64 + bl;
    const int n0   = blockIdx.y * NPB;

    ull sacc2[8];
#pragma unroll
    for (int p = 0; p < 8; ++p) sacc2[p] = 0ull;

    for (int g = 0; g < NPB / 2; ++g) {
        const int n = n0 + g * 2;
        __syncthreads();
        reinterpret_cast<float4*>(sW)[tid] =
            reinterpret_cast<const float4*>(g_Wt + (size_t)n * CL * JDIM)[tid];
        if (tid < 512) {
            int i  = tid >> 8;
            int bb = (tid >> 2) & 63;
            int j2 = (tid & 3) * 2;
            const float2 xv = *reinterpret_cast<const float2*>(
                x + ((size_t)(blockIdx.x * 64 + bb) * NCAP + n + i) * JDIM + j2);
            sx[i][bb * 9 + j2]     = xv.x;
            sx[i][bb * 9 + j2 + 1] = xv.y;
        }
        __syncthreads();

#pragma unroll
        for (int i = 0; i < 2; ++i) {
            const float* wbase = sW + i * CL * JDIM + c * JDIM * LDIM;
            ull u2[8];
#pragma unroll
            for (int p = 0; p < 8; ++p) u2[p] = 0ull;
#pragma unroll
            for (int j = 0; j < JDIM; ++j) {
                float xs = sx[i][bl * 9 + j];
                ull x2 = pk2(xs, xs);
                const ulonglong2* w =
                    reinterpret_cast<const ulonglong2*>(wbase + j * LDIM);
                ulonglong2 wa = w[0], wb = w[1], wc = w[2], wd = w[3];
                u2[0] = fma2(wa.x, x2, u2[0]);
                u2[1] = fma2(wa.y, x2, u2[1]);
                u2[2] = fma2(wb.x, x2, u2[2]);
                u2[3] = fma2(wb.y, x2, u2[3]);
                u2[4] = fma2(wc.x, x2, u2[4]);
                u2[5] = fma2(wc.y, x2, u2[5]);
                u2[6] = fma2(wd.x, x2, u2[6]);
                u2[7] = fma2(wd.y, x2, u2[7]);
            }
            // accumulate s0 partial
#pragma unroll
            for (int p = 0; p < 8; ++p) sacc2[p] = add2(sacc2[p], u2[p]);
            // store u as fp16 [b][c][n][l]
            unsigned int h[8];
#pragma unroll
            for (int p = 0; p < 8; ++p) h[p] = f22h2(u2[p]);
            uint4* up = reinterpret_cast<uint4*>(
                g_u + (((size_t)b * CDIM + c) * NCAP + (n + i)) * LDIM);
            up[0] = make_uint4(h[0], h[1], h[2], h[3]);
            up[1] = make_uint4(h[4], h[5], h[6], h[7]);
        }
    }

    float* dst = g_s + (b * CDIM + c) * LDIM;
#pragma unroll
    for (int p = 0; p < 8; ++p) {
        atomicAdd(dst + 2 * p,     lo2(sacc2[p]));
        atomicAdd(dst + 2 * p + 1, hi2(sacc2[p]));
    }
}

// ---------------------------------------------------------------------------
// Passes 1 & 2: read fp16 u, do routing. Block = one b (128 blocks, 320 thr).
// Warp = c; lanes scan n (G=4 n per thread per barrier group).
// MODE 1: v = squash(s0/C + bias) in prologue; epilogue writes g_v = v0+v1.
// MODE 2: v = g_v; epilogue squashes and writes output.
// ---------------------------------------------------------------------------
template <int MODE>
__global__ __launch_bounds__(320, 1) void pass_ro_kernel(const float* __restrict__ biases,
                                                         float* __restrict__ out) {
    __shared__ float sE[CDIM][128];

    const int lane = threadIdx.x & 31;
    const int c    = threadIdx.x >> 5;      // 0..9
    const int b    = blockIdx.x;

    // prologue: v for this (b,c), replicated across lanes
    float v[LDIM];
    if (MODE == 1) {
        float n2 = 0.0f;
#pragma unroll
        for (int l = 0; l < LDIM; ++l) {
            float s = 0.1f * g_s[(b * CDIM + c) * LDIM + l] + biases[c * LDIM + l];
            v[l] = s; n2 += s * s;
        }
        float f = n2 / (1.0f + n2) / (sqrtf(n2) + 1e-7f);
#pragma unroll
        for (int l = 0; l < LDIM; ++l) v[l] *= f;
    } else {
#pragma unroll
        for (int l = 0; l < LDIM; ++l) v[l] = g_v[(b * CDIM + c) * LDIM + l];
    }
    ull v2[8];
#pragma unroll
    for (int p = 0; p < 8; ++p) v2[p] = pk2(v[2 * p], v[2 * p + 1]);

    ull sacc2[8];
#pragma unroll
    for (int p = 0; p < 8; ++p) sacc2[p] = 0ull;

    const uint4* ubase = reinterpret_cast<const uint4*>(
        g_u + ((size_t)b * CDIM + c) * NCAP * LDIM);   // 2 uint4 per n

    for (int nb = 0; nb < NCAP; nb += 128) {
        uint4 ua[4], ub_[4];
#pragma unroll
        for (int g = 0; g < 4; ++g) {
            size_t idx = (size_t)(nb + g * 32 + lane) * 2;
            ua[g]  = ubase[idx];
            ub_[g] = ubase[idx + 1];
        }
        __syncthreads();   // previous group done reading sE
        float e[4];
#pragma unroll
        for (int g = 0; g < 4; ++g) {
            ull bd2 = 0ull;
            bd2 = fma2(h2f2(ua[g].x),  v2[0], bd2);
            bd2 = fma2(h2f2(ua[g].y),  v2[1], bd2);
            bd2 = fma2(h2f2(ua[g].z),  v2[2], bd2);
            bd2 = fma2(h2f2(ua[g].w),  v2[3], bd2);
            bd2 = fma2(h2f2(ub_[g].x), v2[4], bd2);
            bd2 = fma2(h2f2(ub_[g].y), v2[5], bd2);
            bd2 = fma2(h2f2(ub_[g].z), v2[6], bd2);
            bd2 = fma2(h2f2(ub_[g].w), v2[7], bd2);
            float bd = lo2(bd2) + hi2(bd2);
            e[g] = __expf(bd);          // |bd| small: no max-subtract needed
            sE[c][g * 32 + lane] = e[g];
        }
        __syncthreads();
#pragma unroll
        for (int g = 0; g < 4; ++g) {
            float sum = 0.0f;
#pragma unroll
            for (int cc = 0; cc < CDIM; ++cc) sum += sE[cc][g * 32 + lane];
            float coef = __fdividef(e[g], sum);
            ull c2 = pk2(coef, coef);
            sacc2[0] = fma2(h2f2(ua[g].x),  c2, sacc2[0]);
            sacc2[1] = fma2(h2f2(ua[g].y),  c2, sacc2[1]);
            sacc2[2] = fma2(h2f2(ua[g].z),  c2, sacc2[2]);
            sacc2[3] = fma2(h2f2(ua[g].w),  c2, sacc2[3]);
            sacc2[4] = fma2(h2f2(ub_[g].x), c2, sacc2[4]);
            sacc2[5] = fma2(h2f2(ub_[g].y), c2, sacc2[5]);
            sacc2[6] = fma2(h2f2(ub_[g].z), c2, sacc2[6]);
            sacc2[7] = fma2(h2f2(ub_[g].w), c2, sacc2[7]);
        }
    }

    // reduce sacc across the 32 lanes of this warp
    float sl[LDIM];
#pragma unroll
    for (int p = 0; p < 8; ++p) { sl[2 * p] = lo2(sacc2[p]); sl[2 * p + 1] = hi2(sacc2[p]); }
#pragma unroll
    for (int off = 16; off; off >>= 1)
#pragma unroll
        for (int l = 0; l < LDIM; ++l)
            sl[l] += __shfl_xor_sync(0xFFFFFFFFu, sl[l], off);

    if (lane == 0) {
        float n2 = 0.0f;
#pragma unroll
        for (int l = 0; l < LDIM; ++l) {
            sl[l] += biases[c * LDIM + l];
            n2 += sl[l] * sl[l];
        }
        float f = n2 / (1.0f + n2) / (sqrtf(n2) + 1e-7f);
        if (MODE == 1) {
#pragma unroll
            for (int l = 0; l < LDIM; ++l)
                g_v[(b * CDIM + c) * LDIM + l] = v[l] + f * sl[l];   // v0 + v1
        } else {
#pragma unroll
            for (int l = 0; l < LDIM; ++l)
                out[(b * CDIM + c) * LDIM + l] = f * sl[l];
        }
    }
}

extern "C" void kernel_launch(void* const* d_in, const int* in_sizes, int n_in,
                              void* d_out, int out_size) {
    const float* inputs = (const float*)d_in[0];   // [128,4608,8]
    const float* W      = (const float*)d_in[1];   // [4608,8,160]
    const float* biases = (const float*)d_in[2];   // [10,16]
    float* out = (float*)d_out;                    // [128,10,16]

    transpose_W_kernel<<<NCAP, CL>>>(W);
    zero_s_kernel<<<(BATCH * CDIM * LDIM + 255) / 256, 256>>>();

    dim3 p0Grid(BATCH / 64, NCHUNKS);              // (2, 72)
    pass0_kernel<<<p0Grid, 640>>>(inputs);

    pass_ro_kernel<1><<<BATCH, 320>>>(biases, out);
    pass_ro_kernel<2><<<BATCH, 320>>>(biases, out);
}

// round 4
// speedup vs baseline: 1.1360x; 1.1360x over previous
#include <cuda_runtime.h>
#include <cuda_fp16.h>
#include <math.h>

#define BATCH 128
#define NCAP  4608
#define JDIM  8
#define CDIM  10
#define LDIM  16
#define CL    160            // CDIM*LDIM
#define NPB   64             // n's per block in pass0
#define NCHUNKS (NCAP/NPB)   // 72
#define G0    4              // n's per smem group in pass0
#define NSPLIT 2             // n-range splits in pass_ro

typedef unsigned long long ull;

// Scratch (static device globals; no dynamic allocation allowed)
__device__ __align__(16) float g_Wt[NCAP * CL * JDIM];          // [n][c][j][l]  ~23.6 MB
__device__ __align__(16) __half g_u[(size_t)BATCH * CDIM * NCAP * LDIM]; // 188.7 MB
__device__ __align__(16) float g_s0[BATCH * CDIM * LDIM];
__device__ __align__(16) float g_s1[BATCH * CDIM * LDIM];
__device__ __align__(16) float g_s2[BATCH * CDIM * LDIM];
__device__ __align__(16) float g_v[BATCH * CDIM * LDIM];        // v0+v1 for pass2

// ---- f32x2 packed-math helpers ---------------------------------------------
__device__ __forceinline__ ull pk2(float a, float b) {
    ull r; asm("mov.b64 %0,{%1,%2};" : "=l"(r) : "f"(a), "f"(b)); return r;
}
__device__ __forceinline__ ull fma2(ull a, ull b, ull c) {
    ull d; asm("fma.rn.f32x2 %0,%1,%2,%3;" : "=l"(d) : "l"(a), "l"(b), "l"(c)); return d;
}
__device__ __forceinline__ ull add2(ull a, ull b) {
    ull d; asm("add.rn.f32x2 %0,%1,%2;" : "=l"(d) : "l"(a), "l"(b)); return d;
}
__device__ __forceinline__ float lo2(ull a) {
    float f; asm("{ .reg .b32 h; mov.b64 {%0,h}, %1; }" : "=f"(f) : "l"(a)); return f;
}
__device__ __forceinline__ float hi2(ull a) {
    float f; asm("{ .reg .b32 l; mov.b64 {l,%0}, %1; }" : "=f"(f) : "l"(a)); return f;
}
__device__ __forceinline__ ull h2f2(unsigned int h) {
    __half2 hh = *reinterpret_cast<__half2*>(&h);
    float2 f = __half22float2(hh);
    return pk2(f.x, f.y);
}
__device__ __forceinline__ unsigned int f22h2(ull a) {
    unsigned int h;
    float lo = lo2(a), hi = hi2(a);
    asm("cvt.rn.f16x2.f32 %0, %1, %2;" : "=r"(h) : "f"(hi), "f"(lo));
    return h;
}
__device__ __forceinline__ float squash_factor(float n2) {
    return n2 / (1.0f + n2) / (sqrtf(n2) + 1e-7f);
}

// ---------------------------------------------------------------------------
// Transpose W[n][j][c*16+l] -> Wt[n][c][j][l]
// ---------------------------------------------------------------------------
__global__ void transpose_W_kernel(const float* __restrict__ W) {
    int n  = blockIdx.x;
    int t  = threadIdx.x;         // c*16+l
    int c  = t >> 4, l = t & 15;
    const float* Wn = W + (size_t)n * JDIM * CL;
    float* dst = g_Wt + (size_t)n * CL * JDIM;
#pragma unroll
    for (int j = 0; j < JDIM; ++j)
        dst[(c * JDIM + j) * LDIM + l] = Wn[j * CL + t];
}

__global__ void zero3_kernel() {
    int i = blockIdx.x * blockDim.x + threadIdx.x;
    if (i < BATCH * CDIM * LDIM) { g_s0[i] = 0.0f; g_s1[i] = 0.0f; g_s2[i] = 0.0f; }
}

// ---------------------------------------------------------------------------
// Pass 0: u = x.W -> fp16 g_u [b][c][n][l]; accumulate raw sum_n u into g_s0.
// 320 threads: warp = c (0..9), lane = local b (32 b per block).
// grid (BATCH/32, NCHUNKS) = (4, 72). G0=4 n's per smem group.
// ---------------------------------------------------------------------------
__global__ __launch_bounds__(320, 2) void pass0_kernel(const float* __restrict__ x) {
    __shared__ float sW[G0 * CL * JDIM];    // 20 KB: [i][c][j][l]
    __shared__ float sx[G0][JDIM * 32];     // 4 KB:  [i][j][b]

    const int tid  = threadIdx.x;
    const int lane = tid & 31;
    const int c    = tid >> 5;              // 0..9
    const int b    = blockIdx.x * 32 + lane;
    const int n0   = blockIdx.y * NPB;

    ull sacc2[8];
#pragma unroll
    for (int p = 0; p < 8; ++p) sacc2[p] = 0ull;

    for (int g = 0; g < NPB / G0; ++g) {
        const int n = n0 + g * G0;
        __syncthreads();
        // stage W: G0*1280 floats = 1280 float4; 4 per thread
        {
            const float4* src = reinterpret_cast<const float4*>(g_Wt + (size_t)n * CL * JDIM);
            float4* dst = reinterpret_cast<float4*>(sW);
#pragma unroll
            for (int k = 0; k < 4; ++k) dst[tid + k * 320] = src[tid + k * 320];
        }
        // stage x: G0 n * 32 b * 8 j = 1024 floats, 256 threads x float4
        if (tid < 256) {
            int i  = tid >> 6;
            int rem = tid & 63;
            int bb = rem >> 1;
            int j4 = (rem & 1) * 4;
            const float4 xv = *reinterpret_cast<const float4*>(
                x + ((size_t)(blockIdx.x * 32 + bb) * NCAP + (n + i)) * JDIM + j4);
            sx[i][(j4 + 0) * 32 + bb] = xv.x;
            sx[i][(j4 + 1) * 32 + bb] = xv.y;
            sx[i][(j4 + 2) * 32 + bb] = xv.z;
            sx[i][(j4 + 3) * 32 + bb] = xv.w;
        }
        __syncthreads();

#pragma unroll
        for (int i = 0; i < G0; ++i) {
            const float* wbase = sW + i * CL * JDIM + c * JDIM * LDIM;
            ull u2[8];
#pragma unroll
            for (int p = 0; p < 8; ++p) u2[p] = 0ull;
#pragma unroll
            for (int j = 0; j < JDIM; ++j) {
                float xs = sx[i][j * 32 + lane];
                ull x2 = pk2(xs, xs);
                const ulonglong2* w =
                    reinterpret_cast<const ulonglong2*>(wbase + j * LDIM);
                ulonglong2 wa = w[0], wb = w[1], wc = w[2], wd = w[3];
                u2[0] = fma2(wa.x, x2, u2[0]);
                u2[1] = fma2(wa.y, x2, u2[1]);
                u2[2] = fma2(wb.x, x2, u2[2]);
                u2[3] = fma2(wb.y, x2, u2[3]);
                u2[4] = fma2(wc.x, x2, u2[4]);
                u2[5] = fma2(wc.y, x2, u2[5]);
                u2[6] = fma2(wd.x, x2, u2[6]);
                u2[7] = fma2(wd.y, x2, u2[7]);
            }
#pragma unroll
            for (int p = 0; p < 8; ++p) sacc2[p] = add2(sacc2[p], u2[p]);
            // store u as fp16 [b][c][n][l] (32 contiguous bytes per (b,c,n))
            uint4* up = reinterpret_cast<uint4*>(
                g_u + (((size_t)b * CDIM + c) * NCAP + (n + i)) * LDIM);
            up[0] = make_uint4(f22h2(u2[0]), f22h2(u2[1]), f22h2(u2[2]), f22h2(u2[3]));
            up[1] = make_uint4(f22h2(u2[4]), f22h2(u2[5]), f22h2(u2[6]), f22h2(u2[7]));
        }
    }

    float* dst = g_s0 + (b * CDIM + c) * LDIM;
#pragma unroll
    for (int p = 0; p < 8; ++p) {
        atomicAdd(dst + 2 * p,     lo2(sacc2[p]));
        atomicAdd(dst + 2 * p + 1, hi2(sacc2[p]));
    }
}

// ---------------------------------------------------------------------------
// Passes 1 & 2: read fp16 u, routing. grid (BATCH, NSPLIT), 320 threads.
// Warp = c; lanes scan an n-subrange (G=4 n per thread per barrier group).
// MODE 1: v = squash(s0/C + bias) computed in prologue; partials -> g_s1.
// MODE 2: v = g_v (= v0+v1);                              partials -> g_s2.
// ---------------------------------------------------------------------------
template <int MODE>
__global__ __launch_bounds__(320, 2) void pass_ro_kernel(const float* __restrict__ biases) {
    __shared__ float sE[CDIM][128];

    const int lane = threadIdx.x & 31;
    const int c    = threadIdx.x >> 5;      // 0..9
    const int b    = blockIdx.x;
    const int nbeg = blockIdx.y * (NCAP / NSPLIT);

    // prologue: v for this (b,c) (replicated across lanes; broadcast loads)
    ull v2[8];
    if (MODE == 1) {
        float v[LDIM];
        float n2 = 0.0f;
#pragma unroll
        for (int l = 0; l < LDIM; ++l) {
            float s = 0.1f * g_s0[(b * CDIM + c) * LDIM + l] + biases[c * LDIM + l];
            v[l] = s; n2 += s * s;
        }
        float f = squash_factor(n2);
#pragma unroll
        for (int p = 0; p < 8; ++p) v2[p] = pk2(f * v[2 * p], f * v[2 * p + 1]);
    } else {
#pragma unroll
        for (int p = 0; p < 8; ++p)
            v2[p] = reinterpret_cast<const ull*>(g_v + (b * CDIM + c) * LDIM)[p];
    }

    ull sacc2[8];
#pragma unroll
    for (int p = 0; p < 8; ++p) sacc2[p] = 0ull;

    const uint4* ubase = reinterpret_cast<const uint4*>(
        g_u + ((size_t)b * CDIM + c) * NCAP * LDIM);   // 2 uint4 per n

    for (int nb = nbeg; nb < nbeg + NCAP / NSPLIT; nb += 128) {
        uint4 ua[4], ub_[4];
#pragma unroll
        for (int g = 0; g < 4; ++g) {
            size_t idx = (size_t)(nb + g * 32 + lane) * 2;
            ua[g]  = ubase[idx];
            ub_[g] = ubase[idx + 1];
        }
        __syncthreads();   // previous group done reading sE
        float e[4];
#pragma unroll
        for (int g = 0; g < 4; ++g) {
            ull bd2 = 0ull;
            bd2 = fma2(h2f2(ua[g].x),  v2[0], bd2);
            bd2 = fma2(h2f2(ua[g].y),  v2[1], bd2);
            bd2 = fma2(h2f2(ua[g].z),  v2[2], bd2);
            bd2 = fma2(h2f2(ua[g].w),  v2[3], bd2);
            bd2 = fma2(h2f2(ub_[g].x), v2[4], bd2);
            bd2 = fma2(h2f2(ub_[g].y), v2[5], bd2);
            bd2 = fma2(h2f2(ub_[g].z), v2[6], bd2);
            bd2 = fma2(h2f2(ub_[g].w), v2[7], bd2);
            float bd = lo2(bd2) + hi2(bd2);
            e[g] = __expf(bd);          // |bd| small: no max-subtract needed
            sE[c][g * 32 + lane] = e[g];
        }
        __syncthreads();
#pragma unroll
        for (int g = 0; g < 4; ++g) {
            float sum = 0.0f;
#pragma unroll
            for (int cc = 0; cc < CDIM; ++cc) sum += sE[cc][g * 32 + lane];
            float coef = __fdividef(e[g], sum);
            ull c2 = pk2(coef, coef);
            // re-convert (keeps register count under the 2-block/SM cap)
            sacc2[0] = fma2(h2f2(ua[g].x),  c2, sacc2[0]);
            sacc2[1] = fma2(h2f2(ua[g].y),  c2, sacc2[1]);
            sacc2[2] = fma2(h2f2(ua[g].z),  c2, sacc2[2]);
            sacc2[3] = fma2(h2f2(ua[g].w),  c2, sacc2[3]);
            sacc2[4] = fma2(h2f2(ub_[g].x), c2, sacc2[4]);
            sacc2[5] = fma2(h2f2(ub_[g].y), c2, sacc2[5]);
            sacc2[6] = fma2(h2f2(ub_[g].z), c2, sacc2[6]);
            sacc2[7] = fma2(h2f2(ub_[g].w), c2, sacc2[7]);
        }
    }

    // reduce across the 32 lanes of this warp
    float sl[LDIM];
#pragma unroll
    for (int p = 0; p < 8; ++p) { sl[2 * p] = lo2(sacc2[p]); sl[2 * p + 1] = hi2(sacc2[p]); }
#pragma unroll
    for (int off = 16; off; off >>= 1)
#pragma unroll
        for (int l = 0; l < LDIM; ++l)
            sl[l] += __shfl_xor_sync(0xFFFFFFFFu, sl[l], off);

    if (lane == 0) {
        float* dst = (MODE == 1 ? g_s1 : g_s2) + (b * CDIM + c) * LDIM;
#pragma unroll
        for (int l = 0; l < LDIM; ++l) atomicAdd(dst + l, sl[l]);
    }
}

// ---------------------------------------------------------------------------
// g_v = squash(s0/C + bias) + squash(s1 + bias)     (v0 + v1, for pass 2)
// ---------------------------------------------------------------------------
__global__ void squash_mid_kernel(const float* __restrict__ biases) {
    int idx = blockIdx.x * blockDim.x + threadIdx.x;   // (b*C + c)
    if (idx >= BATCH * CDIM) return;
    int c = idx % CDIM;
    float v0[LDIM], v1[LDIM];
    float n20 = 0.0f, n21 = 0.0f;
#pragma unroll
    for (int l = 0; l < LDIM; ++l) {
        float bias = biases[c * LDIM + l];
        v0[l] = 0.1f * g_s0[idx * LDIM + l] + bias;
        v1[l] = g_s1[idx * LDIM + l] + bias;
        n20 += v0[l] * v0[l];
        n21 += v1[l] * v1[l];
    }
    float f0 = squash_factor(n20), f1 = squash_factor(n21);
#pragma unroll
    for (int l = 0; l < LDIM; ++l)
        g_v[idx * LDIM + l] = f0 * v0[l] + f1 * v1[l];
}

__global__ void squash_out_kernel(const float* __restrict__ biases, float* __restrict__ out) {
    int idx = blockIdx.x * blockDim.x + threadIdx.x;
    if (idx >= BATCH * CDIM) return;
    int c = idx % CDIM;
    float s[LDIM];
    float n2 = 0.0f;
#pragma unroll
    for (int l = 0; l < LDIM; ++l) {
        s[l] = g_s2[idx * LDIM + l] + biases[c * LDIM + l];
        n2 += s[l] * s[l];
    }
    float f = squash_factor(n2);
#pragma unroll
    for (int l = 0; l < LDIM; ++l) out[idx * LDIM + l] = f * s[l];
}

extern "C" void kernel_launch(void* const* d_in, const int* in_sizes, int n_in,
                              void* d_out, int out_size) {
    const float* inputs = (const float*)d_in[0];   // [128,4608,8]
    const float* W      = (const float*)d_in[1];   // [4608,8,160]
    const float* biases = (const float*)d_in[2];   // [10,16]
    float* out = (float*)d_out;                    // [128,10,16]

    transpose_W_kernel<<<NCAP, CL>>>(W);
    zero3_kernel<<<(BATCH * CDIM * LDIM + 255) / 256, 256>>>();

    pass0_kernel<<<dim3(BATCH / 32, NCHUNKS), 320>>>(inputs);      // (4,72)
    pass_ro_kernel<1><<<dim3(BATCH, NSPLIT), 320>>>(biases);
    squash_mid_kernel<<<(BATCH * CDIM + 255) / 256, 256>>>(biases);
    pass_ro_kernel<2><<<dim3(BATCH, NSPLIT), 320>>>(biases);
    squash_out_kernel<<<(BATCH * CDIM + 255) / 256, 256>>>(biases, out);
}

// round 5
// speedup vs baseline: 1.2785x; 1.1254x over previous
#include <cuda_runtime.h>
#include <cuda_fp16.h>
#include <math.h>

#define BATCH 128
#define NCAP  4608
#define JDIM  8
#define CDIM  10
#define LDIM  16
#define CL    160            // CDIM*LDIM
#define NPB   64             // n's per block in pass0
#define NCHUNKS (NCAP/NPB)   // 72
#define G0    4              // n's per smem group in pass0
#define NSPLIT 64            // n-range splits in pass_ro
#define NRANGE (NCAP/NSPLIT) // 72
#define RITER (NRANGE/2)     // 36 iterations of 2 n

typedef unsigned long long ull;

// Scratch (static device globals; no dynamic allocation allowed)
__device__ __align__(16) float g_Wt[NCAP * CL * JDIM];          // [n][c][j][l]  ~23.6 MB
__device__ __align__(16) __half g_u[(size_t)CDIM * NCAP * BATCH * LDIM]; // [c][n][b][l] 188.7 MB
__device__ __align__(16) float g_s0[BATCH * CDIM * LDIM];
__device__ __align__(16) float g_s1[BATCH * CDIM * LDIM];
__device__ __align__(16) float g_s2[BATCH * CDIM * LDIM];

// ---- f32x2 packed-math helpers ---------------------------------------------
__device__ __forceinline__ ull pk2(float a, float b) {
    ull r; asm("mov.b64 %0,{%1,%2};" : "=l"(r) : "f"(a), "f"(b)); return r;
}
__device__ __forceinline__ ull fma2(ull a, ull b, ull c) {
    ull d; asm("fma.rn.f32x2 %0,%1,%2,%3;" : "=l"(d) : "l"(a), "l"(b), "l"(c)); return d;
}
__device__ __forceinline__ ull add2(ull a, ull b) {
    ull d; asm("add.rn.f32x2 %0,%1,%2;" : "=l"(d) : "l"(a), "l"(b)); return d;
}
__device__ __forceinline__ float lo2(ull a) {
    float f; asm("{ .reg .b32 h; mov.b64 {%0,h}, %1; }" : "=f"(f) : "l"(a)); return f;
}
__device__ __forceinline__ float hi2(ull a) {
    float f; asm("{ .reg .b32 l; mov.b64 {l,%0}, %1; }" : "=f"(f) : "l"(a)); return f;
}
__device__ __forceinline__ ull h2f2(unsigned int h) {
    __half2 hh = *reinterpret_cast<__half2*>(&h);
    float2 f = __half22float2(hh);
    return pk2(f.x, f.y);
}
__device__ __forceinline__ unsigned int f22h2(ull a) {
    unsigned int h;
    float lo = lo2(a), hi = hi2(a);
    asm("cvt.rn.f16x2.f32 %0, %1, %2;" : "=r"(h) : "f"(hi), "f"(lo));
    return h;
}
__device__ __forceinline__ float squash_factor(float n2) {
    return n2 / (1.0f + n2) / (sqrtf(n2) + 1e-7f);
}

// ---------------------------------------------------------------------------
// Transpose W[n][j][c*16+l] -> Wt[n][c][j][l]; also zero s accumulators.
// ---------------------------------------------------------------------------
__global__ void transpose_W_kernel(const float* __restrict__ W) {
    int n  = blockIdx.x;
    int t  = threadIdx.x;         // c*16+l
    if (n < 128) {                // fused zeroing: 128*160 = 20480 = BATCH*CDIM*LDIM
        int z = n * CL + t;
        g_s0[z] = 0.0f; g_s1[z] = 0.0f; g_s2[z] = 0.0f;
    }
    int c  = t >> 4, l = t & 15;
    const float* Wn = W + (size_t)n * JDIM * CL;
    float* dst = g_Wt + (size_t)n * CL * JDIM;
#pragma unroll
    for (int j = 0; j < JDIM; ++j)
        dst[(c * JDIM + j) * LDIM + l] = Wn[j * CL + t];
}

// ---------------------------------------------------------------------------
// Pass 0: u = x.W -> fp16 g_u [c][n][b][l] (coalesced stores: lane = b);
// accumulate raw sum_n u into g_s0 (uniform softmax(0) -> scale 1/C later).
// 320 threads: warp = c, lane = local b. grid (BATCH/32, NCHUNKS) = (4,72).
// ---------------------------------------------------------------------------
__global__ __launch_bounds__(320, 2) void pass0_kernel(const float* __restrict__ x) {
    __shared__ float sW[G0 * CL * JDIM];    // 20 KB: [i][c][j][l]
    __shared__ float sx[G0][JDIM * 32];     // 4 KB:  [i][j][b]

    const int tid  = threadIdx.x;
    const int lane = tid & 31;
    const int c    = tid >> 5;              // 0..9
    const int b    = blockIdx.x * 32 + lane;
    const int n0   = blockIdx.y * NPB;

    ull sacc2[8];
#pragma unroll
    for (int p = 0; p < 8; ++p) sacc2[p] = 0ull;

    for (int g = 0; g < NPB / G0; ++g) {
        const int n = n0 + g * G0;
        __syncthreads();
        {
            const float4* src = reinterpret_cast<const float4*>(g_Wt + (size_t)n * CL * JDIM);
            float4* dst = reinterpret_cast<float4*>(sW);
#pragma unroll
            for (int k = 0; k < 4; ++k) dst[tid + k * 320] = src[tid + k * 320];
        }
        if (tid < 256) {
            int i  = tid >> 6;
            int rem = tid & 63;
            int bb = rem >> 1;
            int j4 = (rem & 1) * 4;
            const float4 xv = *reinterpret_cast<const float4*>(
                x + ((size_t)(blockIdx.x * 32 + bb) * NCAP + (n + i)) * JDIM + j4);
            sx[i][(j4 + 0) * 32 + bb] = xv.x;
            sx[i][(j4 + 1) * 32 + bb] = xv.y;
            sx[i][(j4 + 2) * 32 + bb] = xv.z;
            sx[i][(j4 + 3) * 32 + bb] = xv.w;
        }
        __syncthreads();

#pragma unroll
        for (int i = 0; i < G0; ++i) {
            const float* wbase = sW + i * CL * JDIM + c * JDIM * LDIM;
            ull u2[8];
#pragma unroll
            for (int p = 0; p < 8; ++p) u2[p] = 0ull;
#pragma unroll
            for (int j = 0; j < JDIM; ++j) {
                float xs = sx[i][j * 32 + lane];
                ull x2 = pk2(xs, xs);
                const ulonglong2* w =
                    reinterpret_cast<const ulonglong2*>(wbase + j * LDIM);
                ulonglong2 wa = w[0], wb = w[1], wc = w[2], wd = w[3];
                u2[0] = fma2(wa.x, x2, u2[0]);
                u2[1] = fma2(wa.y, x2, u2[1]);
                u2[2] = fma2(wb.x, x2, u2[2]);
                u2[3] = fma2(wb.y, x2, u2[3]);
                u2[4] = fma2(wc.x, x2, u2[4]);
                u2[5] = fma2(wc.y, x2, u2[5]);
                u2[6] = fma2(wd.x, x2, u2[6]);
                u2[7] = fma2(wd.y, x2, u2[7]);
            }
#pragma unroll
            for (int p = 0; p < 8; ++p) sacc2[p] = add2(sacc2[p], u2[p]);
            // store u as fp16 [c][n][b][l]: warp writes 1024B contiguous
            uint4* up = reinterpret_cast<uint4*>(
                g_u + (((size_t)c * NCAP + (n + i)) * BATCH + b) * LDIM);
            up[0] = make_uint4(f22h2(u2[0]), f22h2(u2[1]), f22h2(u2[2]), f22h2(u2[3]));
            up[1] = make_uint4(f22h2(u2[4]), f22h2(u2[5]), f22h2(u2[6]), f22h2(u2[7]));
        }
    }

    float* dst = g_s0 + (b * CDIM + c) * LDIM;
#pragma unroll
    for (int p = 0; p < 8; ++p) {
        atomicAdd(dst + 2 * p,     lo2(sacc2[p]));
        atomicAdd(dst + 2 * p + 1, hi2(sacc2[p]));
    }
}

// ---------------------------------------------------------------------------
// Passes 1 & 2: thread = (b,c), lane = b, scans an n-subrange (2 n per iter,
// double-buffered loads, 1 barrier per iter via parity sE).
// MODE 1: v = squash(s0/C + bias);           partials -> g_s1.
// MODE 2: v = squash(s0/C+bias)+squash(s1+bias); partials -> g_s2.
// grid (BATCH/32, NSPLIT) = (4, 64), 320 threads.
// ---------------------------------------------------------------------------
template <int MODE>
__global__ __launch_bounds__(320, 2) void pass_ro_kernel(const float* __restrict__ biases) {
    __shared__ float sE[2][CDIM][2][32];    // parity, c, i, local b

    const int lane = threadIdx.x & 31;      // local b
    const int c    = threadIdx.x >> 5;      // 0..9
    const int b    = blockIdx.x * 32 + lane;
    const int nbeg = blockIdx.y * NRANGE;

    // prologue: v for this (b,c)
    ull v2[8];
    {
        float v[LDIM];
        float n20 = 0.0f;
#pragma unroll
        for (int l = 0; l < LDIM; ++l) {
            float s = 0.1f * g_s0[(b * CDIM + c) * LDIM + l] + biases[c * LDIM + l];
            v[l] = s; n20 += s * s;
        }
        float f0 = squash_factor(n20);
        if (MODE == 1) {
#pragma unroll
            for (int p = 0; p < 8; ++p) v2[p] = pk2(f0 * v[2 * p], f0 * v[2 * p + 1]);
        } else {
            float w[LDIM];
            float n21 = 0.0f;
#pragma unroll
            for (int l = 0; l < LDIM; ++l) {
                float s = g_s1[(b * CDIM + c) * LDIM + l] + biases[c * LDIM + l];
                w[l] = s; n21 += s * s;
            }
            float f1 = squash_factor(n21);
#pragma unroll
            for (int p = 0; p < 8; ++p)
                v2[p] = pk2(f0 * v[2 * p] + f1 * w[2 * p],
                            f0 * v[2 * p + 1] + f1 * w[2 * p + 1]);
        }
    }

    ull sacc2[8];
#pragma unroll
    for (int p = 0; p < 8; ++p) sacc2[p] = 0ull;

    // u base for (c, b): element (c,n,b) at ((c*NCAP+n)*BATCH+b)*2 uint4s
    const uint4* ubase = reinterpret_cast<const uint4*>(g_u)
                       + ((size_t)c * NCAP * BATCH + b) * 2;
    const size_t nstr = (size_t)BATCH * 2;   // uint4 stride per n

    uint4 ca0 = ubase[(size_t)nbeg * nstr];
    uint4 ca1 = ubase[(size_t)nbeg * nstr + 1];
    uint4 cb0 = ubase[(size_t)(nbeg + 1) * nstr];
    uint4 cb1 = ubase[(size_t)(nbeg + 1) * nstr + 1];

    for (int it = 0; it < RITER; ++it) {
        // prefetch next pair (clamped)
        const int np = nbeg + ((it + 1 < RITER) ? (it + 1) * 2 : it * 2);
        uint4 na0 = ubase[(size_t)np * nstr];
        uint4 na1 = ubase[(size_t)np * nstr + 1];
        uint4 nb0 = ubase[(size_t)(np + 1) * nstr];
        uint4 nb1 = ubase[(size_t)(np + 1) * nstr + 1];

        // bd + e for both n
        {
            ull bd2 = 0ull;
            bd2 = fma2(h2f2(ca0.x), v2[0], bd2);
            bd2 = fma2(h2f2(ca0.y), v2[1], bd2);
            bd2 = fma2(h2f2(ca0.z), v2[2], bd2);
            bd2 = fma2(h2f2(ca0.w), v2[3], bd2);
            bd2 = fma2(h2f2(ca1.x), v2[4], bd2);
            bd2 = fma2(h2f2(ca1.y), v2[5], bd2);
            bd2 = fma2(h2f2(ca1.z), v2[6], bd2);
            bd2 = fma2(h2f2(ca1.w), v2[7], bd2);
            sE[it & 1][c][0][lane] = __expf(lo2(bd2) + hi2(bd2));
        }
        {
            ull bd2 = 0ull;
            bd2 = fma2(h2f2(cb0.x), v2[0], bd2);
            bd2 = fma2(h2f2(cb0.y), v2[1], bd2);
            bd2 = fma2(h2f2(cb0.z), v2[2], bd2);
            bd2 = fma2(h2f2(cb0.w), v2[3], bd2);
            bd2 = fma2(h2f2(cb1.x), v2[4], bd2);
            bd2 = fma2(h2f2(cb1.y), v2[5], bd2);
            bd2 = fma2(h2f2(cb1.z), v2[6], bd2);
            bd2 = fma2(h2f2(cb1.w), v2[7], bd2);
            sE[it & 1][c][1][lane] = __expf(lo2(bd2) + hi2(bd2));
        }
        __syncthreads();
        {
            float s0 = 0.0f, s1 = 0.0f;
#pragma unroll
            for (int cc = 0; cc < CDIM; ++cc) {
                s0 += sE[it & 1][cc][0][lane];
                s1 += sE[it & 1][cc][1][lane];
            }
            float c0 = __fdividef(sE[it & 1][c][0][lane], s0);
            float c1 = __fdividef(sE[it & 1][c][1][lane], s1);
            ull cc0 = pk2(c0, c0), cc1 = pk2(c1, c1);
            sacc2[0] = fma2(h2f2(ca0.x), cc0, sacc2[0]);
            sacc2[1] = fma2(h2f2(ca0.y), cc0, sacc2[1]);
            sacc2[2] = fma2(h2f2(ca0.z), cc0, sacc2[2]);
            sacc2[3] = fma2(h2f2(ca0.w), cc0, sacc2[3]);
            sacc2[4] = fma2(h2f2(ca1.x), cc0, sacc2[4]);
            sacc2[5] = fma2(h2f2(ca1.y), cc0, sacc2[5]);
            sacc2[6] = fma2(h2f2(ca1.z), cc0, sacc2[6]);
            sacc2[7] = fma2(h2f2(ca1.w), cc0, sacc2[7]);
            sacc2[0] = fma2(h2f2(cb0.x), cc1, sacc2[0]);
            sacc2[1] = fma2(h2f2(cb0.y), cc1, sacc2[1]);
            sacc2[2] = fma2(h2f2(cb0.z), cc1, sacc2[2]);
            sacc2[3] = fma2(h2f2(cb0.w), cc1, sacc2[3]);
            sacc2[4] = fma2(h2f2(cb1.x), cc1, sacc2[4]);
            sacc2[5] = fma2(h2f2(cb1.y), cc1, sacc2[5]);
            sacc2[6] = fma2(h2f2(cb1.z), cc1, sacc2[6]);
            sacc2[7] = fma2(h2f2(cb1.w), cc1, sacc2[7]);
        }
        ca0 = na0; ca1 = na1; cb0 = nb0; cb1 = nb1;
    }

    float* dst = (MODE == 1 ? g_s1 : g_s2) + (b * CDIM + c) * LDIM;
#pragma unroll
    for (int p = 0; p < 8; ++p) {
        atomicAdd(dst + 2 * p,     lo2(sacc2[p]));
        atomicAdd(dst + 2 * p + 1, hi2(sacc2[p]));
    }
}

__global__ void squash_out_kernel(const float* __restrict__ biases, float* __restrict__ out) {
    int idx = blockIdx.x * blockDim.x + threadIdx.x;   // (b*C + c)
    if (idx >= BATCH * CDIM) return;
    int c = idx % CDIM;
    float s[LDIM];
    float n2 = 0.0f;
#pragma unroll
    for (int l = 0; l < LDIM; ++l) {
        s[l] = g_s2[idx * LDIM + l] + biases[c * LDIM + l];
        n2 += s[l] * s[l];
    }
    float f = squash_factor(n2);
#pragma unroll
    for (int l = 0; l < LDIM; ++l) out[idx * LDIM + l] = f * s[l];
}

extern "C" void kernel_launch(void* const* d_in, const int* in_sizes, int n_in,
                              void* d_out, int out_size) {
    const float* inputs = (const float*)d_in[0];   // [128,4608,8]
    const float* W      = (const float*)d_in[1];   // [4608,8,160]
    const float* biases = (const float*)d_in[2];   // [10,16]
    float* out = (float*)d_out;                    // [128,10,16]

    transpose_W_kernel<<<NCAP, CL>>>(W);           // also zeroes s0/s1/s2
    pass0_kernel<<<dim3(BATCH / 32, NCHUNKS), 320>>>(inputs);      // (4,72)
    pass_ro_kernel<1><<<dim3(BATCH / 32, NSPLIT), 320>>>(biases);  // (4,64)
    pass_ro_kernel<2><<<dim3(BATCH / 32, NSPLIT), 320>>>(biases);  // (4,64)
    squash_out_kernel<<<(BATCH * CDIM + 255) / 256, 256>>>(biases, out);
}

// round 6
// speedup vs baseline: 1.3722x; 1.0733x over previous
#include <cuda_runtime.h>
#include <cuda_fp16.h>
#include <math.h>

#define BATCH 128
#define NCAP  4608
#define JDIM  8
#define CDIM  10
#define LDIM  16
#define CL    160            // CDIM*LDIM
#define NPB   64             // n's per block in pass0
#define NCHUNKS (NCAP/NPB)   // 72
#define G0    4              // n's per smem group in pass0
#define NSPLIT 72            // n-range splits in pass_ro
#define NRANGE (NCAP/NSPLIT) // 64
#define PAIRS  (NRANGE/2)    // 32 pairs of n per block

typedef unsigned long long ull;

// Scratch (static device globals; no dynamic allocation allowed)
__device__ __align__(16) float g_Wt[NCAP * CL * JDIM];          // [n][c][j][l]  ~23.6 MB
__device__ __align__(32) __half g_u[(size_t)CDIM * NCAP * BATCH * LDIM]; // [c][n][b][l] 188.7 MB
__device__ __align__(16) float g_s0[BATCH * CDIM * LDIM];
__device__ __align__(16) float g_s1[BATCH * CDIM * LDIM];
__device__ __align__(16) float g_s2[BATCH * CDIM * LDIM];

struct __align__(32) H16 { uint4 a, b; };   // 32B = one (b,c,n) u row in fp16

// ---- f32x2 packed-math helpers ---------------------------------------------
__device__ __forceinline__ ull pk2(float a, float b) {
    ull r; asm("mov.b64 %0,{%1,%2};" : "=l"(r) : "f"(a), "f"(b)); return r;
}
__device__ __forceinline__ ull fma2(ull a, ull b, ull c) {
    ull d; asm("fma.rn.f32x2 %0,%1,%2,%3;" : "=l"(d) : "l"(a), "l"(b), "l"(c)); return d;
}
__device__ __forceinline__ ull add2(ull a, ull b) {
    ull d; asm("add.rn.f32x2 %0,%1,%2;" : "=l"(d) : "l"(a), "l"(b)); return d;
}
__device__ __forceinline__ float lo2(ull a) {
    float f; asm("{ .reg .b32 h; mov.b64 {%0,h}, %1; }" : "=f"(f) : "l"(a)); return f;
}
__device__ __forceinline__ float hi2(ull a) {
    float f; asm("{ .reg .b32 l; mov.b64 {l,%0}, %1; }" : "=f"(f) : "l"(a)); return f;
}
__device__ __forceinline__ ull h2f2(unsigned int h) {
    __half2 hh = *reinterpret_cast<__half2*>(&h);
    float2 f = __half22float2(hh);
    return pk2(f.x, f.y);
}
__device__ __forceinline__ unsigned int f22h2(ull a) {
    unsigned int h;
    float lo = lo2(a), hi = hi2(a);
    asm("cvt.rn.f16x2.f32 %0, %1, %2;" : "=r"(h) : "f"(hi), "f"(lo));
    return h;
}
__device__ __forceinline__ float squash_factor(float n2) {
    return n2 / (1.0f + n2) / (sqrtf(n2) + 1e-7f);
}
__device__ __forceinline__ void cpasync16(unsigned int sdst, const void* gsrc) {
    asm volatile("cp.async.cg.shared.global [%0], [%1], 16;" :: "r"(sdst), "l"(gsrc) : "memory");
}
__device__ __forceinline__ void cpasync_commit() {
    asm volatile("cp.async.commit_group;" ::: "memory");
}
__device__ __forceinline__ void cpasync_wait1() {
    asm volatile("cp.async.wait_group 1;" ::: "memory");
}

// ---------------------------------------------------------------------------
// Transpose W[n][j][c*16+l] -> Wt[n][c][j][l]; also zero s accumulators.
// ---------------------------------------------------------------------------
__global__ void transpose_W_kernel(const float* __restrict__ W) {
    int n  = blockIdx.x;
    int t  = threadIdx.x;         // c*16+l
    if (n < 128) {                // fused zeroing: 128*160 = BATCH*CDIM*LDIM
        int z = n * CL + t;
        g_s0[z] = 0.0f; g_s1[z] = 0.0f; g_s2[z] = 0.0f;
    }
    int c  = t >> 4, l = t & 15;
    const float* Wn = W + (size_t)n * JDIM * CL;
    float* dst = g_Wt + (size_t)n * CL * JDIM;
#pragma unroll
    for (int j = 0; j < JDIM; ++j)
        dst[(c * JDIM + j) * LDIM + l] = Wn[j * CL + t];
}

// ---------------------------------------------------------------------------
// Pass 0: u = x.W -> fp16 g_u [c][n][b][l]; accumulate raw sum_n u into g_s0.
// 320 threads: warp = c, lane = local b. grid (BATCH/32, NCHUNKS) = (4,72).
// ---------------------------------------------------------------------------
__global__ __launch_bounds__(320, 2) void pass0_kernel(const float* __restrict__ x) {
    __shared__ float sW[G0 * CL * JDIM];    // 20 KB: [i][c][j][l]
    __shared__ float sx[G0][JDIM * 32];     // 4 KB:  [i][j][b]

    const int tid  = threadIdx.x;
    const int lane = tid & 31;
    const int c    = tid >> 5;              // 0..9
    const int b    = blockIdx.x * 32 + lane;
    const int n0   = blockIdx.y * NPB;

    ull sacc2[8];
#pragma unroll
    for (int p = 0; p < 8; ++p) sacc2[p] = 0ull;

    for (int g = 0; g < NPB / G0; ++g) {
        const int n = n0 + g * G0;
        __syncthreads();
        {
            const float4* src = reinterpret_cast<const float4*>(g_Wt + (size_t)n * CL * JDIM);
            float4* dst = reinterpret_cast<float4*>(sW);
#pragma unroll
            for (int k = 0; k < 4; ++k) dst[tid + k * 320] = src[tid + k * 320];
        }
        if (tid < 256) {
            int i  = tid >> 6;
            int rem = tid & 63;
            int bb = rem >> 1;
            int j4 = (rem & 1) * 4;
            const float4 xv = *reinterpret_cast<const float4*>(
                x + ((size_t)(blockIdx.x * 32 + bb) * NCAP + (n + i)) * JDIM + j4);
            sx[i][(j4 + 0) * 32 + bb] = xv.x;
            sx[i][(j4 + 1) * 32 + bb] = xv.y;
            sx[i][(j4 + 2) * 32 + bb] = xv.z;
            sx[i][(j4 + 3) * 32 + bb] = xv.w;
        }
        __syncthreads();

#pragma unroll
        for (int i = 0; i < G0; ++i) {
            const float* wbase = sW + i * CL * JDIM + c * JDIM * LDIM;
            ull u2[8];
#pragma unroll
            for (int p = 0; p < 8; ++p) u2[p] = 0ull;
#pragma unroll
            for (int j = 0; j < JDIM; ++j) {
                float xs = sx[i][j * 32 + lane];
                ull x2 = pk2(xs, xs);
                const ulonglong2* w =
                    reinterpret_cast<const ulonglong2*>(wbase + j * LDIM);
                ulonglong2 wa = w[0], wb = w[1], wc = w[2], wd = w[3];
                u2[0] = fma2(wa.x, x2, u2[0]);
                u2[1] = fma2(wa.y, x2, u2[1]);
                u2[2] = fma2(wb.x, x2, u2[2]);
                u2[3] = fma2(wb.y, x2, u2[3]);
                u2[4] = fma2(wc.x, x2, u2[4]);
                u2[5] = fma2(wc.y, x2, u2[5]);
                u2[6] = fma2(wd.x, x2, u2[6]);
                u2[7] = fma2(wd.y, x2, u2[7]);
            }
#pragma unroll
            for (int p = 0; p < 8; ++p) sacc2[p] = add2(sacc2[p], u2[p]);
            // one 32B store per (b,c,n): warp writes 1024B contiguous
            H16 val;
            val.a = make_uint4(f22h2(u2[0]), f22h2(u2[1]), f22h2(u2[2]), f22h2(u2[3]));
            val.b = make_uint4(f22h2(u2[4]), f22h2(u2[5]), f22h2(u2[6]), f22h2(u2[7]));
            *reinterpret_cast<H16*>(
                g_u + (((size_t)c * NCAP + (n + i)) * BATCH + b) * LDIM) = val;
        }
    }

    float* dst = g_s0 + (b * CDIM + c) * LDIM;
#pragma unroll
    for (int p = 0; p < 8; ++p) {
        atomicAdd(dst + 2 * p,     lo2(sacc2[p]));
        atomicAdd(dst + 2 * p + 1, hi2(sacc2[p]));
    }
}

// ---------------------------------------------------------------------------
// Passes 1 & 2: cp.async-pipelined read of fp16 u.
// Block: 320 thr, warp = c, lane = local b; scans NRANGE=64 n (32 pairs).
// 2-stage smem pipeline, refilled 2 pairs ahead. 2 barriers per pair.
// MODE 1: v = squash(s0/C+bias);                partials -> g_s1.
// MODE 2: v = squash(s0/C+bias)+squash(s1+bias); partials -> g_s2.
// grid (BATCH/32, NSPLIT) = (4, 72).
// ---------------------------------------------------------------------------
template <int MODE>
__global__ __launch_bounds__(320, 2) void pass_ro_kernel(const float* __restrict__ biases) {
    __shared__ __align__(16) __half sU[2][2][CDIM][32][LDIM];  // 40 KB
    __shared__ float sE[CDIM][2][32];                          // 2.5 KB

    const int tid  = threadIdx.x;
    const int lane = tid & 31;              // local b
    const int c    = tid >> 5;              // 0..9
    const int b    = blockIdx.x * 32 + lane;
    const int Bb   = blockIdx.x * 32;
    const int nbeg = blockIdx.y * NRANGE;

    // prologue: v for this (b,c)
    ull v2[8];
    {
        float v[LDIM];
        float n20 = 0.0f;
#pragma unroll
        for (int l = 0; l < LDIM; ++l) {
            float s = 0.1f * g_s0[(b * CDIM + c) * LDIM + l] + biases[c * LDIM + l];
            v[l] = s; n20 += s * s;
        }
        float f0 = squash_factor(n20);
        if (MODE == 1) {
#pragma unroll
            for (int p = 0; p < 8; ++p) v2[p] = pk2(f0 * v[2 * p], f0 * v[2 * p + 1]);
        } else {
            float w[LDIM];
            float n21 = 0.0f;
#pragma unroll
            for (int l = 0; l < LDIM; ++l) {
                float s = g_s1[(b * CDIM + c) * LDIM + l] + biases[c * LDIM + l];
                w[l] = s; n21 += s * s;
            }
            float f1 = squash_factor(n21);
#pragma unroll
            for (int p = 0; p < 8; ++p)
                v2[p] = pk2(f0 * v[2 * p] + f1 * w[2 * p],
                            f0 * v[2 * p + 1] + f1 * w[2 * p + 1]);
        }
    }

    const unsigned int su_base =
        (unsigned int)__cvta_generic_to_shared(&sU[0][0][0][0][0]);

    // fill stage s with n-pair p: 1280 x 16B chunks, 4 per thread
    auto fill = [&](int s, int p) {
        const int n0 = nbeg + p * 2;
#pragma unroll
        for (int q = 0; q < 4; ++q) {
            int k    = tid + q * 320;          // 0..1279
            int i    = (k >= 640) ? 1 : 0;
            int r    = k - i * 640;
            int cp   = r >> 6;
            int rem  = r & 63;
            int bp   = rem >> 1;
            int half = (rem & 1) << 3;         // 0 or 8 halves
            const __half* gsrc = g_u +
                (((size_t)cp * NCAP + (n0 + i)) * BATCH + (Bb + bp)) * LDIM + half;
            unsigned int sdst = su_base +
                ((((s * 2 + i) * CDIM + cp) * 32 + bp) * LDIM + half) * 2;
            cpasync16(sdst, gsrc);
        }
    };

    ull sacc2[8];
#pragma unroll
    for (int p = 0; p < 8; ++p) sacc2[p] = 0ull;

    fill(0, 0); cpasync_commit();
    fill(1, 1); cpasync_commit();

    for (int it = 0; it < PAIRS; ++it) {
        const int st = it & 1;
        cpasync_wait1();
        __syncthreads();                       // stage st ready for all warps

        const uint4* pa = reinterpret_cast<const uint4*>(&sU[st][0][c][lane][0]);
        uint4 a0 = pa[0], a1 = pa[1];
        const uint4* pb = reinterpret_cast<const uint4*>(&sU[st][1][c][lane][0]);
        uint4 b0 = pb[0], b1 = pb[1];

        {
            ull bd2 = 0ull;
            bd2 = fma2(h2f2(a0.x), v2[0], bd2);
            bd2 = fma2(h2f2(a0.y), v2[1], bd2);
            bd2 = fma2(h2f2(a0.z), v2[2], bd2);
            bd2 = fma2(h2f2(a0.w), v2[3], bd2);
            bd2 = fma2(h2f2(a1.x), v2[4], bd2);
            bd2 = fma2(h2f2(a1.y), v2[5], bd2);
            bd2 = fma2(h2f2(a1.z), v2[6], bd2);
            bd2 = fma2(h2f2(a1.w), v2[7], bd2);
            sE[c][0][lane] = __expf(lo2(bd2) + hi2(bd2));
        }
        {
            ull bd2 = 0ull;
            bd2 = fma2(h2f2(b0.x), v2[0], bd2);
            bd2 = fma2(h2f2(b0.y), v2[1], bd2);
            bd2 = fma2(h2f2(b0.z), v2[2], bd2);
            bd2 = fma2(h2f2(b0.w), v2[3], bd2);
            bd2 = fma2(h2f2(b1.x), v2[4], bd2);
            bd2 = fma2(h2f2(b1.y), v2[5], bd2);
            bd2 = fma2(h2f2(b1.z), v2[6], bd2);
            bd2 = fma2(h2f2(b1.w), v2[7], bd2);
            sE[c][1][lane] = __expf(lo2(bd2) + hi2(bd2));
        }
        __syncthreads();                       // sE ready; stage st fully consumed
        {
            float s0 = 0.0f, s1 = 0.0f;
#pragma unroll
            for (int cc = 0; cc < CDIM; ++cc) {
                s0 += sE[cc][0][lane];
                s1 += sE[cc][1][lane];
            }
            float c0 = __fdividef(sE[c][0][lane], s0);
            float c1 = __fdividef(sE[c][1][lane], s1);
            ull cc0 = pk2(c0, c0), cc1 = pk2(c1, c1);
            sacc2[0] = fma2(h2f2(a0.x), cc0, sacc2[0]);
            sacc2[1] = fma2(h2f2(a0.y), cc0, sacc2[1]);
            sacc2[2] = fma2(h2f2(a0.z), cc0, sacc2[2]);
            sacc2[3] = fma2(h2f2(a0.w), cc0, sacc2[3]);
            sacc2[4] = fma2(h2f2(a1.x), cc0, sacc2[4]);
            sacc2[5] = fma2(h2f2(a1.y), cc0, sacc2[5]);
            sacc2[6] = fma2(h2f2(a1.z), cc0, sacc2[6]);
            sacc2[7] = fma2(h2f2(a1.w), cc0, sacc2[7]);
            sacc2[0] = fma2(h2f2(b0.x), cc1, sacc2[0]);
            sacc2[1] = fma2(h2f2(b0.y), cc1, sacc2[1]);
            sacc2[2] = fma2(h2f2(b0.z), cc1, sacc2[2]);
            sacc2[3] = fma2(h2f2(b0.w), cc1, sacc2[3]);
            sacc2[4] = fma2(h2f2(b1.x), cc1, sacc2[4]);
            sacc2[5] = fma2(h2f2(b1.y), cc1, sacc2[5]);
            sacc2[6] = fma2(h2f2(b1.z), cc1, sacc2[6]);
            sacc2[7] = fma2(h2f2(b1.w), cc1, sacc2[7]);
        }

        if (it + 2 < PAIRS) fill(st, it + 2);
        cpasync_commit();                      // commit (possibly empty) keeps count
    }

    float* dst = (MODE == 1 ? g_s1 : g_s2) + (b * CDIM + c) * LDIM;
#pragma unroll
    for (int p = 0; p < 8; ++p) {
        atomicAdd(dst + 2 * p,     lo2(sacc2[p]));
        atomicAdd(dst + 2 * p + 1, hi2(sacc2[p]));
    }
}

__global__ void squash_out_kernel(const float* __restrict__ biases, float* __restrict__ out) {
    int idx = blockIdx.x * blockDim.x + threadIdx.x;   // (b*C + c)
    if (idx >= BATCH * CDIM) return;
    int c = idx % CDIM;
    float s[LDIM];
    float n2 = 0.0f;
#pragma unroll
    for (int l = 0; l < LDIM; ++l) {
        s[l] = g_s2[idx * LDIM + l] + biases[c * LDIM + l];
        n2 += s[l] * s[l];
    }
    float f = squash_factor(n2);
#pragma unroll
    for (int l = 0; l < LDIM; ++l) out[idx * LDIM + l] = f * s[l];
}

extern "C" void kernel_launch(void* const* d_in, const int* in_sizes, int n_in,
                              void* d_out, int out_size) {
    const float* inputs = (const float*)d_in[0];   // [128,4608,8]
    const float* W      = (const float*)d_in[1];   // [4608,8,160]
    const float* biases = (const float*)d_in[2];   // [10,16]
    float* out = (float*)d_out;                    // [128,10,16]

    transpose_W_kernel<<<NCAP, CL>>>(W);           // also zeroes s0/s1/s2
    pass0_kernel<<<dim3(BATCH / 32, NCHUNKS), 320>>>(inputs);      // (4,72)
    pass_ro_kernel<1><<<dim3(BATCH / 32, NSPLIT), 320>>>(biases);  // (4,72)
    pass_ro_kernel<2><<<dim3(BATCH / 32, NSPLIT), 320>>>(biases);  // (4,72)
    squash_out_kernel<<<(BATCH * CDIM + 255) / 256, 256>>>(biases, out);
}

// round 9
// speedup vs baseline: 1.7542x; 1.2783x over previous
#include <cuda_runtime.h>
#include <cuda_fp16.h>
#include <math.h>

#define BATCH 128
#define NCAP  4608
#define JDIM  8
#define CDIM  10
#define LDIM  16
#define CL    160             // CDIM*LDIM
#define NSPLIT 72             // n-range splits in pass_ro
#define NRANGE (NCAP/NSPLIT)  // 64
#define PAIRS  (NRANGE/2)     // 32 pairs of n per pass_ro block
#define NBLK0  144            // pass0 blocks
#define NPB0   (NCAP/NBLK0)   // 32 n per pass0 block

typedef unsigned long long ull;

// Scratch (static device globals; no dynamic allocation allowed)
__device__ __align__(16) __half g_Wh[(size_t)NCAP * CL * JDIM];          // [n][cl][8j] fp16
__device__ __align__(32) __half g_u[(size_t)CDIM * NCAP * BATCH * LDIM]; // [c][n][b][l] 188.7 MB
__device__ __align__(16) float g_s0[BATCH * CDIM * LDIM];
__device__ __align__(16) float g_s1[BATCH * CDIM * LDIM];
__device__ __align__(16) float g_s2[BATCH * CDIM * LDIM];

// ---- f32x2 packed-math helpers ---------------------------------------------
__device__ __forceinline__ ull pk2(float a, float b) {
    ull r; asm("mov.b64 %0,{%1,%2};" : "=l"(r) : "f"(a), "f"(b)); return r;
}
__device__ __forceinline__ ull fma2(ull a, ull b, ull c) {
    ull d; asm("fma.rn.f32x2 %0,%1,%2,%3;" : "=l"(d) : "l"(a), "l"(b), "l"(c)); return d;
}
__device__ __forceinline__ float lo2(ull a) {
    float f; asm("{ .reg .b32 h; mov.b64 {%0,h}, %1; }" : "=f"(f) : "l"(a)); return f;
}
__device__ __forceinline__ float hi2(ull a) {
    float f; asm("{ .reg .b32 l; mov.b64 {l,%0}, %1; }" : "=f"(f) : "l"(a)); return f;
}
__device__ __forceinline__ ull h2f2(unsigned int h) {
    __half2 hh = *reinterpret_cast<__half2*>(&h);
    float2 f = __half22float2(hh);
    return pk2(f.x, f.y);
}
__device__ __forceinline__ unsigned int cvt2h(float lo, float hi) {
    unsigned int h;
    asm("cvt.rn.f16x2.f32 %0, %1, %2;" : "=r"(h) : "f"(hi), "f"(lo));
    return h;
}
__device__ __forceinline__ float squash_factor(float n2) {
    return n2 / (1.0f + n2) / (sqrtf(n2) + 1e-7f);
}
__device__ __forceinline__ void cpasync16(unsigned int sdst, const void* gsrc) {
    asm volatile("cp.async.cg.shared.global [%0], [%1], 16;" :: "r"(sdst), "l"(gsrc) : "memory");
}
__device__ __forceinline__ void cpasync_commit() {
    asm volatile("cp.async.commit_group;" ::: "memory");
}
__device__ __forceinline__ void cpasync_wait1() {
    asm volatile("cp.async.wait_group 1;" ::: "memory");
}
__device__ __forceinline__ void cpasync_wait0() {
    asm volatile("cp.async.wait_group 0;" ::: "memory");
}
__device__ __forceinline__ unsigned int smem_u32(const void* p) {
    return (unsigned int)__cvta_generic_to_shared(p);
}

// ---- HMMA helpers (base ISA: works on plain sm_103 target) ------------------
__device__ __forceinline__ void ldsm_x2(unsigned int& r0, unsigned int& r1, unsigned int a) {
    asm volatile("ldmatrix.sync.aligned.m8n8.x2.shared.b16 {%0,%1}, [%2];"
                 : "=r"(r0), "=r"(r1) : "r"(a));
}
__device__ __forceinline__ void ldsm_x4(unsigned int& r0, unsigned int& r1,
                                        unsigned int& r2, unsigned int& r3, unsigned int a) {
    asm volatile("ldmatrix.sync.aligned.m8n8.x4.shared.b16 {%0,%1,%2,%3}, [%4];"
                 : "=r"(r0), "=r"(r1), "=r"(r2), "=r"(r3) : "r"(a));
}
__device__ __forceinline__ void mma_16n8k8(float* c, unsigned int a0, unsigned int a1,
                                           unsigned int b0) {
    asm volatile("mma.sync.aligned.m16n8k8.row.col.f32.f16.f16.f32 "
                 "{%0,%1,%2,%3}, {%4,%5}, {%6}, {%7,%7,%7,%7};"
                 : "=f"(c[0]), "=f"(c[1]), "=f"(c[2]), "=f"(c[3])
                 : "r"(a0), "r"(a1), "r"(b0), "f"(0.0f));
}

// ---------------------------------------------------------------------------
// W prep: W[n][j][cl] fp32 -> g_Wh[n][cl][8j] fp16 (16B per row); zero s bufs.
// ---------------------------------------------------------------------------
__global__ void transpose_W_kernel(const float* __restrict__ W) {
    int n = blockIdx.x;
    int cl = threadIdx.x;     // 0..159
    if (n < 128) {            // fused zeroing (128*160 = BATCH*CDIM*LDIM)
        int z = n * CL + cl;
        g_s0[z] = 0.0f; g_s1[z] = 0.0f; g_s2[z] = 0.0f;
    }
    const float* Wn = W + (size_t)n * JDIM * CL;
    unsigned int h[4];
#pragma unroll
    for (int p = 0; p < 4; ++p)
        h[p] = cvt2h(Wn[(2 * p) * CL + cl], Wn[(2 * p + 1) * CL + cl]);
    *reinterpret_cast<uint4*>(g_Wh + ((size_t)n * CL + cl) * JDIM) =
        make_uint4(h[0], h[1], h[2], h[3]);
}

// ---------------------------------------------------------------------------
// Pass 0 (HMMA): per n, u[128b x 160cl] = x[128x8] * Wh[160x8]^T via 160
// m16n8k8 tiles. 512 thr (16 warps): warp (w%8) = m-tile, (w/8) = cl half.
// s0 accumulated in fp32 regs, atomically flushed once. u -> fp16 g_u[c][n][b][l].
// Double-buffered smem, 1 barrier per n. grid 144, 32 n per block.
// ---------------------------------------------------------------------------
__global__ __launch_bounds__(512, 1) void pass0_mma(const float* __restrict__ x) {
    __shared__ __align__(16) __half sA[2][128 * JDIM];   // 4 KB: [b][8j]
    __shared__ __align__(16) __half sB[2][CL * JDIM];    // 5 KB: [cl][8j]

    const int tid  = threadIdx.x;
    const int lane = tid & 31;
    const int wid  = tid >> 5;            // 0..15
    const int w8   = wid & 7;             // m-tile (b rows 16*w8..)
    const int hh   = wid >> 3;            // cl-half (tiles 10*hh..)
    const int n0   = blockIdx.x * NPB0;

    float s0acc[40];
#pragma unroll
    for (int i = 0; i < 40; ++i) s0acc[i] = 0.0f;

    auto fillA = [&](int buf, int n) {
        if (tid < 256) {
            int b = tid >> 1, jh = (tid & 1) * 4;
            const float4 xv = *reinterpret_cast<const float4*>(
                x + ((size_t)b * NCAP + n) * JDIM + jh);
            *reinterpret_cast<uint2*>(&sA[buf][b * JDIM + jh]) =
                make_uint2(cvt2h(xv.x, xv.y), cvt2h(xv.z, xv.w));
        }
    };
    auto fillB = [&](int buf, int n) {
        if (tid >= 256 && tid < 256 + CL) {
            int cl = tid - 256;
            cpasync16(smem_u32(&sB[buf][cl * JDIM]),
                      g_Wh + ((size_t)n * CL + cl) * JDIM);
        }
    };

    fillA(0, n0); fillB(0, n0); cpasync_commit();

    // ldmatrix source addresses (per-lane row pointers)
    const unsigned int aaddr  = smem_u32(&sA[0][(w8 * 16 + (lane & 15)) * JDIM]);
    const unsigned int baddr0 = smem_u32(&sB[0][(hh * 80 + lane) * JDIM]);
    const unsigned int baddr1 = smem_u32(&sB[0][(hh * 80 + 32 + lane) * JDIM]);
    const unsigned int baddr2 = smem_u32(&sB[0][(hh * 80 + 64 + (lane & 15)) * JDIM]);
    const unsigned int strA = 128 * JDIM * 2;   // bytes per A buffer
    const unsigned int strB = CL * JDIM * 2;    // bytes per B buffer

    const int brow = w8 * 16 + (lane >> 2);
    const int lodd = (lane & 3) * 2;

    for (int i = 0; i < NPB0; ++i) {
        const int buf = i & 1;
        const int n = n0 + i;
        cpasync_wait0();
        __syncthreads();                   // fill(buf) complete; prev reads done
        if (i + 1 < NPB0) { fillA(buf ^ 1, n + 1); fillB(buf ^ 1, n + 1); }
        cpasync_commit();

        unsigned int a0, a1, bf[10];
        ldsm_x2(a0, a1, aaddr + buf * strA);
        ldsm_x4(bf[0], bf[1], bf[2], bf[3], baddr0 + buf * strB);
        ldsm_x4(bf[4], bf[5], bf[6], bf[7], baddr1 + buf * strB);
        ldsm_x2(bf[8], bf[9], baddr2 + buf * strB);

        const size_t nbase = (size_t)n * BATCH * LDIM + (size_t)brow * LDIM + lodd;
#pragma unroll
        for (int tt = 0; tt < 10; ++tt) {
            float c4[4];
            mma_16n8k8(c4, a0, a1, bf[tt]);
            s0acc[tt * 4 + 0] += c4[0];
            s0acc[tt * 4 + 1] += c4[1];
            s0acc[tt * 4 + 2] += c4[2];
            s0acc[tt * 4 + 3] += c4[3];
            const int g = hh * 10 + tt;
            const int cc = g >> 1;
            const int l8 = (g & 1) * 8;
            const size_t off = (size_t)cc * ((size_t)NCAP * BATCH * LDIM) + nbase + l8;
            *reinterpret_cast<unsigned int*>(g_u + off) = cvt2h(c4[0], c4[1]);
            *reinterpret_cast<unsigned int*>(g_u + off + 8 * LDIM) = cvt2h(c4[2], c4[3]);
        }
    }

    // flush s0 partials (thread owns unique (b,c,l) pairs within block)
#pragma unroll
    for (int tt = 0; tt < 10; ++tt) {
        const int g = hh * 10 + tt;
        const int cc = g >> 1;
        const int l8 = (g & 1) * 8;
        float* d0 = g_s0 + (brow * CDIM + cc) * LDIM + l8 + lodd;
        atomicAdd(d0,     s0acc[tt * 4 + 0]);
        atomicAdd(d0 + 1, s0acc[tt * 4 + 1]);
        float* d1 = g_s0 + ((brow + 8) * CDIM + cc) * LDIM + l8 + lodd;
        atomicAdd(d1,     s0acc[tt * 4 + 2]);
        atomicAdd(d1 + 1, s0acc[tt * 4 + 3]);
    }
}

// ---------------------------------------------------------------------------
// Passes 1 & 2: cp.async-pipelined read of fp16 u (unchanged from R6 pass).
// ---------------------------------------------------------------------------
template <int MODE>
__global__ __launch_bounds__(320, 2) void pass_ro_kernel(const float* __restrict__ biases) {
    __shared__ __align__(16) __half sU[2][2][CDIM][32][LDIM];  // 40 KB
    __shared__ float sE[CDIM][2][32];

    const int tid  = threadIdx.x;
    const int lane = tid & 31;              // local b
    const int c    = tid >> 5;              // 0..9
    const int b    = blockIdx.x * 32 + lane;
    const int Bb   = blockIdx.x * 32;
    const int nbeg = blockIdx.y * NRANGE;

    ull v2[8];
    {
        float v[LDIM];
        float n20 = 0.0f;
#pragma unroll
        for (int l = 0; l < LDIM; ++l) {
            float s = 0.1f * g_s0[(b * CDIM + c) * LDIM + l] + biases[c * LDIM + l];
            v[l] = s; n20 += s * s;
        }
        float f0 = squash_factor(n20);
        if (MODE == 1) {
#pragma unroll
            for (int p = 0; p < 8; ++p) v2[p] = pk2(f0 * v[2 * p], f0 * v[2 * p + 1]);
        } else {
            float w[LDIM];
            float n21 = 0.0f;
#pragma unroll
            for (int l = 0; l < LDIM; ++l) {
                float s = g_s1[(b * CDIM + c) * LDIM + l] + biases[c * LDIM + l];
                w[l] = s; n21 += s * s;
            }
            float f1 = squash_factor(n21);
#pragma unroll
            for (int p = 0; p < 8; ++p)
                v2[p] = pk2(f0 * v[2 * p] + f1 * w[2 * p],
                            f0 * v[2 * p + 1] + f1 * w[2 * p + 1]);
        }
    }

    const unsigned int su_base = smem_u32(&sU[0][0][0][0][0]);

    auto fill = [&](int s, int p) {
        const int n0 = nbeg + p * 2;
#pragma unroll
        for (int q = 0; q < 4; ++q) {
            int k    = tid + q * 320;
            int i    = (k >= 640) ? 1 : 0;
            int r    = k - i * 640;
            int cp   = r >> 6;
            int rem  = r & 63;
            int bp   = rem >> 1;
            int half = (rem & 1) << 3;
            const __half* gsrc = g_u +
                (((size_t)cp * NCAP + (n0 + i)) * BATCH + (Bb + bp)) * LDIM + half;
            unsigned int sdst = su_base +
                ((((s * 2 + i) * CDIM + cp) * 32 + bp) * LDIM + half) * 2;
            cpasync16(sdst, gsrc);
        }
    };

    ull sacc2[8];
#pragma unroll
    for (int p = 0; p < 8; ++p) sacc2[p] = 0ull;

    fill(0, 0); cpasync_commit();
    fill(1, 1); cpasync_commit();

    for (int it = 0; it < PAIRS; ++it) {
        const int st = it & 1;
        cpasync_wait1();
        __syncthreads();

        const uint4* pa = reinterpret_cast<const uint4*>(&sU[st][0][c][lane][0]);
        uint4 a0 = pa[0], a1 = pa[1];
        const uint4* pb = reinterpret_cast<const uint4*>(&sU[st][1][c][lane][0]);
        uint4 b0 = pb[0], b1 = pb[1];

        {
            ull bd2 = 0ull;
            bd2 = fma2(h2f2(a0.x), v2[0], bd2);
            bd2 = fma2(h2f2(a0.y), v2[1], bd2);
            bd2 = fma2(h2f2(a0.z), v2[2], bd2);
            bd2 = fma2(h2f2(a0.w), v2[3], bd2);
            bd2 = fma2(h2f2(a1.x), v2[4], bd2);
            bd2 = fma2(h2f2(a1.y), v2[5], bd2);
            bd2 = fma2(h2f2(a1.z), v2[6], bd2);
            bd2 = fma2(h2f2(a1.w), v2[7], bd2);
            sE[c][0][lane] = __expf(lo2(bd2) + hi2(bd2));
        }
        {
            ull bd2 = 0ull;
            bd2 = fma2(h2f2(b0.x), v2[0], bd2);
            bd2 = fma2(h2f2(b0.y), v2[1], bd2);
            bd2 = fma2(h2f2(b0.z), v2[2], bd2);
            bd2 = fma2(h2f2(b0.w), v2[3], bd2);
            bd2 = fma2(h2f2(b1.x), v2[4], bd2);
            bd2 = fma2(h2f2(b1.y), v2[5], bd2);
            bd2 = fma2(h2f2(b1.z), v2[6], bd2);
            bd2 = fma2(h2f2(b1.w), v2[7], bd2);
            sE[c][1][lane] = __expf(lo2(bd2) + hi2(bd2));
        }
        __syncthreads();
        {
            float s0 = 0.0f, s1 = 0.0f;
#pragma unroll
            for (int cc = 0; cc < CDIM; ++cc) {
                s0 += sE[cc][0][lane];
                s1 += sE[cc][1][lane];
            }
            float c0 = __fdividef(sE[c][0][lane], s0);
            float c1 = __fdividef(sE[c][1][lane], s1);
            ull cc0 = pk2(c0, c0), cc1 = pk2(c1, c1);
            sacc2[0] = fma2(h2f2(a0.x), cc0, sacc2[0]);
            sacc2[1] = fma2(h2f2(a0.y), cc0, sacc2[1]);
            sacc2[2] = fma2(h2f2(a0.z), cc0, sacc2[2]);
            sacc2[3] = fma2(h2f2(a0.w), cc0, sacc2[3]);
            sacc2[4] = fma2(h2f2(a1.x), cc0, sacc2[4]);
            sacc2[5] = fma2(h2f2(a1.y), cc0, sacc2[5]);
            sacc2[6] = fma2(h2f2(a1.z), cc0, sacc2[6]);
            sacc2[7] = fma2(h2f2(a1.w), cc0, sacc2[7]);
            sacc2[0] = fma2(h2f2(b0.x), cc1, sacc2[0]);
            sacc2[1] = fma2(h2f2(b0.y), cc1, sacc2[1]);
            sacc2[2] = fma2(h2f2(b0.z), cc1, sacc2[2]);
            sacc2[3] = fma2(h2f2(b0.w), cc1, sacc2[3]);
            sacc2[4] = fma2(h2f2(b1.x), cc1, sacc2[4]);
            sacc2[5] = fma2(h2f2(b1.y), cc1, sacc2[5]);
            sacc2[6] = fma2(h2f2(b1.z), cc1, sacc2[6]);
            sacc2[7] = fma2(h2f2(b1.w), cc1, sacc2[7]);
        }

        if (it + 2 < PAIRS) fill(st, it + 2);
        cpasync_commit();
    }

    float* dst = (MODE == 1 ? g_s1 : g_s2) + (b * CDIM + c) * LDIM;
#pragma unroll
    for (int p = 0; p < 8; ++p) {
        atomicAdd(dst + 2 * p,     lo2(sacc2[p]));
        atomicAdd(dst + 2 * p + 1, hi2(sacc2[p]));
    }
}

__global__ void squash_out_kernel(const float* __restrict__ biases, float* __restrict__ out) {
    int idx = blockIdx.x * blockDim.x + threadIdx.x;   // (b*C + c)
    if (idx >= BATCH * CDIM) return;
    int c = idx % CDIM;
    float s[LDIM];
    float n2 = 0.0f;
#pragma unroll
    for (int l = 0; l < LDIM; ++l) {
        s[l] = g_s2[idx * LDIM + l] + biases[c * LDIM + l];
        n2 += s[l] * s[l];
    }
    float f = squash_factor(n2);
#pragma unroll
    for (int l = 0; l < LDIM; ++l) out[idx * LDIM + l] = f * s[l];
}

extern "C" void kernel_launch(void* const* d_in, const int* in_sizes, int n_in,
                              void* d_out, int out_size) {
    const float* inputs = (const float*)d_in[0];   // [128,4608,8]
    const float* W      = (const float*)d_in[1];   // [4608,8,160]
    const float* biases = (const float*)d_in[2];   // [10,16]
    float* out = (float*)d_out;                    // [128,10,16]

    transpose_W_kernel<<<NCAP, CL>>>(W);           // also zeroes s0/s1/s2
    pass0_mma<<<NBLK0, 512>>>(inputs);
    pass_ro_kernel<1><<<dim3(BATCH / 32, NSPLIT), 320>>>(biases);  // (4,72)
    pass_ro_kernel<2><<<dim3(BATCH / 32, NSPLIT), 320>>>(biases);  // (4,72)
    squash_out_kernel<<<(BATCH * CDIM + 255) / 256, 256>>>(biases, out);
}